// round 4
// baseline (speedup 1.0000x reference)
#include <cuda_runtime.h>
#include <cstdint>

typedef unsigned long long u64;
typedef unsigned int u32;

#define NIMG   8
#define NANCH  25200
#define NCH    85
#define NC     80
#define CONF   0.96f
#define IOUT   0.45f
#define CLSCAP 64
#define KEPTCAP 2048
#define DETS   300
#define NBIN   4096
#define CONTCAP 1024
#define SB0    0x3F75C290u   // smallest float bits with s > 0.96f
#define FULL   0xFFFFFFFFu

// Device scratch (zero-initialized; k_nms_out resets counters each replay).
__device__ int g_ccount[NIMG * NC];
__device__ u64 g_clist[NIMG * NC * CLSCAP];

// ---------------------------------------------------------------------------
// K1: filter. Block compacts its 256 anchors' obj-hits into smem, then the
// 8 warps expand hits in parallel (classes across lanes), scattering candidate
// keys into per-(image,class) lists.
// Key = (score_bits << 32) | ~flat_idx  -> desc order == jax top_k order.
// ---------------------------------------------------------------------------
__global__ __launch_bounds__(256) void k_filter(const float* __restrict__ pred) {
    __shared__ int   s_anch[256];
    __shared__ float s_obj[256];
    __shared__ int   s_n;

    int img    = blockIdx.y;
    int anchor = blockIdx.x * 256 + threadIdx.x;
    int warp   = threadIdx.x >> 5;
    int lane   = threadIdx.x & 31;

    if (threadIdx.x == 0) s_n = 0;
    __syncthreads();

    float obj = 0.f;
    if (anchor < NANCH)
        obj = __ldg(pred + ((size_t)img * NANCH + anchor) * NCH + 4);
    if (obj > CONF) {
        int p = atomicAdd(&s_n, 1);
        s_anch[p] = anchor;
        s_obj[p]  = obj;
    }
    __syncthreads();

    int n = s_n;
    for (int j = warp; j < n; j += 8) {
        int   a = s_anch[j];
        float o = s_obj[j];
        const float* row = pred + ((size_t)img * NANCH + a) * NCH + 5;
        #pragma unroll
        for (int r = 0; r < 3; r++) {
            int c = lane + r * 32;
            float s = (c < NC) ? __ldg(row + c) * o : 0.f;
            if (s > CONF) {
                int pos = atomicAdd(&g_ccount[img * NC + c], 1);
                if (pos < CLSCAP) {
                    u32 idx = (u32)(a * NC + c);
                    g_clist[(img * NC + c) * CLSCAP + pos] =
                        ((u64)__float_as_uint(s) << 32) | (u32)(~idx);
                }
            }
        }
    }
}

// Warp-register bitonic compare-exchange step.
__device__ __forceinline__ u64 ce(u64 v, int j, bool desc, int lane) {
    u64 q = __shfl_xor_sync(FULL, v, j);
    bool keepmax = (((lane & j) == 0) == desc);
    bool vbig = v > q;
    return (keepmax == vbig) ? v : q;
}

// ---------------------------------------------------------------------------
// K2 (fused): per image (1 block, 1024 threads):
//   Phase A: 32 warps do per-class register-sort + greedy NMS (cross-class
//            IoU == 0 exactly due to the label*4 offset), appending kept keys
//            to a smem list.
//   Phase B: 4096-bin score histogram + suffix scan -> exact top-300
//            selection; output rank by brute-force comparison among the
//            ~305 contenders (keys unique -> exact); emit rows + zero-fill.
// Dyn smem: [0,16384) u64 kept[2048] | [16384,32768) u32 hist[4096] (reused
// in-place as suffix counts) | [32768,40960) u64 cont[1024]
// ---------------------------------------------------------------------------
#define SMEM_BYTES 40960

__global__ __launch_bounds__(1024) void k_nms_out(const float* __restrict__ pred,
                                                  float* __restrict__ out) {
    extern __shared__ char smem[];
    u64* s_kept = (u64*)smem;
    u32* hist   = (u32*)(smem + 16384);
    u64* s_cont = (u64*)(smem + 32768);
    __shared__ int s_kcnt, s_ccnt;
    __shared__ u32 wsums[32];

    int img  = blockIdx.x;
    int tid  = threadIdx.x;
    int lane = tid & 31;
    int warp = tid >> 5;

    if (tid == 0) { s_kcnt = 0; s_ccnt = 0; }
    __syncthreads();

    // ---------------- Phase A: per-class NMS ----------------
    for (int c = warp; c < NC; c += 32) {
        int cnt = g_ccount[img * NC + c];
        if (cnt > CLSCAP) cnt = CLSCAP;
        if (lane == 0) g_ccount[img * NC + c] = 0;  // clean for next replay

        if (cnt > 0) {
            const u64* lst = &g_clist[(img * NC + c) * CLSCAP];
            u64 k0 = (lane < cnt)      ? lst[lane]      : 0ull;
            u64 k1 = (lane + 32 < cnt) ? lst[lane + 32] : 0ull;

            // Bitonic sort 64 descending (e0 = lane, e1 = lane+32).
            #pragma unroll
            for (int k = 2; k <= 16; k <<= 1) {
                #pragma unroll
                for (int j = k >> 1; j > 0; j >>= 1) {
                    bool d = ((lane & k) == 0);
                    k0 = ce(k0, j, d, lane);
                    k1 = ce(k1, j, d, lane);
                }
            }
            #pragma unroll
            for (int j = 16; j > 0; j >>= 1) {
                k0 = ce(k0, j, true, lane);
                k1 = ce(k1, j, false, lane);
            }
            {
                u64 lo = (k0 < k1) ? k0 : k1;
                u64 hi = (k0 < k1) ? k1 : k0;
                k0 = hi; k1 = lo;
            }
            #pragma unroll
            for (int j = 16; j > 0; j >>= 1) {
                k0 = ce(k0, j, true, lane);
                k1 = ce(k1, j, true, lane);
            }

            // Decode boxes.
            float x10, y10, x20, y20, x11, y11, x21, y21;
            {
                u32 idx = ~(u32)k0;
                if (lane < cnt) {
                    int a = idx / NC;
                    const float* p = pred + ((size_t)img * NANCH + a) * NCH;
                    float cx = __ldg(p), cy = __ldg(p + 1);
                    float w  = __ldg(p + 2), h = __ldg(p + 3);
                    x10 = cx - 0.5f * w; y10 = cy - 0.5f * h;
                    x20 = cx + 0.5f * w; y20 = cy + 0.5f * h;
                } else { x10 = y10 = x20 = y20 = 0.f; }
            }
            {
                u32 idx = ~(u32)k1;
                if (lane + 32 < cnt) {
                    int a = idx / NC;
                    const float* p = pred + ((size_t)img * NANCH + a) * NCH;
                    float cx = __ldg(p), cy = __ldg(p + 1);
                    float w  = __ldg(p + 2), h = __ldg(p + 3);
                    x11 = cx - 0.5f * w; y11 = cy - 0.5f * h;
                    x21 = cx + 0.5f * w; y21 = cy + 0.5f * h;
                } else { x11 = y11 = x21 = y21 = 0.f; }
            }

            u64 alive = (cnt >= 64) ? ~0ull : ((1ull << cnt) - 1ull);
            for (int i = 0; i < cnt; i++) {
                if (!((alive >> i) & 1ull)) continue;
                bool hi = (i >= 32);
                int  sl = i & 31;
                float sx1 = hi ? x11 : x10, sy1 = hi ? y11 : y10;
                float sx2 = hi ? x21 : x20, sy2 = hi ? y21 : y20;
                float ax1 = __shfl_sync(FULL, sx1, sl);
                float ay1 = __shfl_sync(FULL, sy1, sl);
                float ax2 = __shfl_sync(FULL, sx2, sl);
                float ay2 = __shfl_sync(FULL, sy2, sl);
                float areaA = (ax2 - ax1) * (ay2 - ay1);

                float iw0 = fminf(ax2, x20) - fmaxf(ax1, x10);
                float ih0 = fminf(ay2, y20) - fmaxf(ay1, y10);
                float in0 = fmaxf(iw0, 0.f) * fmaxf(ih0, 0.f);
                float ar0 = (x20 - x10) * (y20 - y10);
                float iou0 = in0 / (areaA + ar0 - in0 + 1e-9f);

                float iw1 = fminf(ax2, x21) - fmaxf(ax1, x11);
                float ih1 = fminf(ay2, y21) - fmaxf(ay1, y11);
                float in1 = fmaxf(iw1, 0.f) * fmaxf(ih1, 0.f);
                float ar1 = (x21 - x11) * (y21 - y11);
                float iou1 = in1 / (areaA + ar1 - in1 + 1e-9f);

                u32 m0 = __ballot_sync(FULL, (lane > i) && (iou0 > IOUT));
                u32 m1 = __ballot_sync(FULL, ((lane + 32) > i) && (iou1 > IOUT));
                alive &= ~(((u64)m1 << 32) | (u64)m0);
            }

            // Append kept keys to smem list.
            u32 klo = (u32)alive, khi = (u32)(alive >> 32);
            int tot = __popc(klo) + __popc(khi);
            int base = 0;
            if (lane == 0) base = atomicAdd(&s_kcnt, tot);
            base = __shfl_sync(FULL, base, 0);
            if ((klo >> lane) & 1u) {
                int p = base + __popc(klo & ((1u << lane) - 1u));
                if (p < KEPTCAP) s_kept[p] = k0;
            }
            if ((khi >> lane) & 1u) {
                int p = base + __popc(klo) + __popc(khi & ((1u << lane) - 1u));
                if (p < KEPTCAP) s_kept[p] = k1;
            }
        }
    }
    __syncthreads();

    // ---------------- Phase B: exact top-300 + emit ----------------
    int M = s_kcnt;
    if (M > KEPTCAP) M = KEPTCAP;

    for (int i = tid; i < NBIN; i += 1024) hist[i] = 0;
    __syncthreads();
    for (int i = tid; i < M; i += 1024) {
        u32 h = ((u32)(s_kept[i] >> 32) - SB0) >> 8;
        atomicAdd(&hist[h], 1u);
    }
    __syncthreads();

    // Suffix-exclusive scan over 4096 bins, in place (each thread owns 4 bins).
    int b0i = 4 * tid;
    u32 c0 = hist[b0i], c1 = hist[b0i + 1], c2 = hist[b0i + 2], c3 = hist[b0i + 3];
    u32 T = c0 + c1 + c2 + c3;
    u32 v = T;
    #pragma unroll
    for (int o = 1; o < 32; o <<= 1) {
        u32 u = __shfl_down_sync(FULL, v, o);
        if (lane + o < 32) v += u;
    }
    u32 exw = v - T;
    if (lane == 0) wsums[warp] = v;
    __syncthreads();
    if (warp == 0) {
        u32 wv = wsums[lane];
        u32 s = wv;
        #pragma unroll
        for (int o = 1; o < 32; o <<= 1) {
            u32 u = __shfl_down_sync(FULL, s, o);
            if (lane + o < 32) s += u;
        }
        wsums[lane] = s - wv;
    }
    __syncthreads();
    u32 above = wsums[warp] + exw;
    hist[b0i + 3] = above;
    hist[b0i + 2] = above + c3;
    hist[b0i + 1] = above + c3 + c2;
    hist[b0i + 0] = above + c3 + c2 + c1;
    __syncthreads();

    // Select contenders: rank < 300 is only possible if strictly-above < 300.
    bool selAll = (M <= DETS);
    for (int i = tid; i < M; i += 1024) {
        u64 k = s_kept[i];
        u32 h = ((u32)(k >> 32) - SB0) >> 8;
        if (selAll || hist[h] < DETS) {
            int p = atomicAdd(&s_ccnt, 1);
            if (p < CONTCAP) s_cont[p] = k;
        }
    }
    __syncthreads();
    int S = s_ccnt; if (S > CONTCAP) S = CONTCAP;

    // Exact rank among contenders (keys unique), write row at rank.
    if (tid < S) {
        u64 key = s_cont[tid];
        int rank = 0;
        for (int j = 0; j < S; j++) rank += (s_cont[j] > key) ? 1 : 0;
        if (rank < DETS) {
            u32 idx = ~(u32)key;
            int a   = idx / NC;
            int cls = idx - a * NC;
            const float* p = pred + ((size_t)img * NANCH + a) * NCH;
            float cx = __ldg(p), cy = __ldg(p + 1);
            float w  = __ldg(p + 2), h = __ldg(p + 3);
            float* o = out + ((size_t)img * DETS + rank) * 6;
            o[0] = cx - 0.5f * w; o[1] = cy - 0.5f * h;
            o[2] = cx + 0.5f * w; o[3] = cy + 0.5f * h;
            o[4] = __uint_as_float((u32)(key >> 32));
            o[5] = (float)cls;
        }
    }

    // Zero-fill rows [min(M,300), 300).
    int K = (M < DETS) ? M : DETS;
    for (int r = K + tid; r < DETS; r += 1024) {
        float* o = out + ((size_t)img * DETS + r) * 6;
        o[0] = 0.f; o[1] = 0.f; o[2] = 0.f; o[3] = 0.f; o[4] = 0.f; o[5] = 0.f;
    }
}

extern "C" void kernel_launch(void* const* d_in, const int* in_sizes, int n_in,
                              void* d_out, int out_size) {
    const float* pred = (const float*)d_in[0];
    float* out = (float*)d_out;

    dim3 g1((NANCH + 255) / 256, NIMG);
    k_filter<<<g1, 256>>>(pred);
    k_nms_out<<<NIMG, 1024, SMEM_BYTES>>>(pred, out);
}

// round 5
// speedup vs baseline: 1.9756x; 1.9756x over previous
#include <cuda_runtime.h>
#include <cstdint>

typedef unsigned long long u64;
typedef unsigned int u32;

#define NIMG   8
#define NANCH  25200
#define NCH    85
#define NC     80
#define CONF   0.96f
#define IOUT   0.45f
#define CLSCAP 64
#define KEPTCAP 4096
#define DETS   300
#define NBIN   4096
#define CONTCAP 1024
#define SB0    0x3F75C290u   // smallest float bits with s > 0.96f
#define FULL   0xFFFFFFFFu

// Device scratch (zero-initialized; kernels reset counters after last use so
// every graph replay starts clean).
__device__ int g_ccount[NIMG * NC];
__device__ u64 g_clist[NIMG * NC * CLSCAP];
__device__ int g_kcount[NIMG];
__device__ u64 g_kept[NIMG * KEPTCAP];

// ---------------------------------------------------------------------------
// K1: filter. Block compacts its 256 anchors' obj-hits into smem, then the
// 8 warps expand hits in parallel (classes across lanes), scattering candidate
// keys into per-(image,class) lists.
// Key = (score_bits << 32) | ~flat_idx  -> desc order == jax top_k order.
// ---------------------------------------------------------------------------
__global__ __launch_bounds__(256) void k_filter(const float* __restrict__ pred) {
    __shared__ int   s_anch[256];
    __shared__ float s_obj[256];
    __shared__ int   s_n;

    int img    = blockIdx.y;
    int anchor = blockIdx.x * 256 + threadIdx.x;
    int warp   = threadIdx.x >> 5;
    int lane   = threadIdx.x & 31;

    if (threadIdx.x == 0) s_n = 0;
    __syncthreads();

    float obj = 0.f;
    if (anchor < NANCH)
        obj = __ldg(pred + ((size_t)img * NANCH + anchor) * NCH + 4);
    if (obj > CONF) {
        int p = atomicAdd(&s_n, 1);
        s_anch[p] = anchor;
        s_obj[p]  = obj;
    }
    __syncthreads();

    int n = s_n;
    for (int j = warp; j < n; j += 8) {
        int   a = s_anch[j];
        float o = s_obj[j];
        const float* row = pred + ((size_t)img * NANCH + a) * NCH + 5;
        #pragma unroll
        for (int r = 0; r < 3; r++) {
            int c = lane + r * 32;
            float s = (c < NC) ? __ldg(row + c) * o : 0.f;
            if (s > CONF) {
                int pos = atomicAdd(&g_ccount[img * NC + c], 1);
                if (pos < CLSCAP) {
                    u32 idx = (u32)(a * NC + c);
                    g_clist[(img * NC + c) * CLSCAP + pos] =
                        ((u64)__float_as_uint(s) << 32) | (u32)(~idx);
                }
            }
        }
    }
}

// Warp-register bitonic compare-exchange step.
__device__ __forceinline__ u64 ce(u64 v, int j, bool desc, int lane) {
    u64 q = __shfl_xor_sync(FULL, v, j);
    bool keepmax = (((lane & j) == 0) == desc);
    bool vbig = v > q;
    return (keepmax == vbig) ? v : q;
}

__device__ __forceinline__ void decode_box(const float* __restrict__ pred,
                                           int img, u64 key, bool valid,
                                           float& x1, float& y1,
                                           float& x2, float& y2) {
    if (valid) {
        u32 idx = ~(u32)key;
        int a = idx / NC;
        const float* p = pred + ((size_t)img * NANCH + a) * NCH;
        float cx = __ldg(p), cy = __ldg(p + 1);
        float w  = __ldg(p + 2), h = __ldg(p + 3);
        x1 = cx - 0.5f * w; y1 = cy - 0.5f * h;
        x2 = cx + 0.5f * w; y2 = cy + 0.5f * h;
    } else { x1 = y1 = x2 = y2 = 0.f; }
}

// ---------------------------------------------------------------------------
// K2: one warp per (image, class): register sort + greedy NMS, append kept
// keys to per-image global list. Cross-class IoU == 0 exactly (label*4
// offset), so per-class greedy NMS is exact. Fast path for cnt <= 32.
// ---------------------------------------------------------------------------
__global__ __launch_bounds__(256) void k_nms(const float* __restrict__ pred) {
    int img  = blockIdx.x;
    int warp = threadIdx.x >> 5;
    int lane = threadIdx.x & 31;
    int c    = blockIdx.y * 8 + warp;

    int cnt = g_ccount[img * NC + c];
    if (cnt > CLSCAP) cnt = CLSCAP;
    if (lane == 0) g_ccount[img * NC + c] = 0;  // clean for next replay
    if (cnt == 0) return;

    const u64* lst = &g_clist[(img * NC + c) * CLSCAP];

    if (cnt <= 32) {
        // ---- fast path: 32-element register sort + NMS ----
        u64 k0 = (lane < cnt) ? lst[lane] : 0ull;
        #pragma unroll
        for (int k = 2; k <= 16; k <<= 1) {
            #pragma unroll
            for (int j = k >> 1; j > 0; j >>= 1)
                k0 = ce(k0, j, ((lane & k) == 0), lane);
        }
        #pragma unroll
        for (int j = 16; j > 0; j >>= 1)
            k0 = ce(k0, j, true, lane);

        float x1, y1, x2, y2;
        decode_box(pred, img, k0, lane < cnt, x1, y1, x2, y2);

        u32 alive = (cnt >= 32) ? FULL : ((1u << cnt) - 1u);
        for (int i = 0; i < cnt; i++) {
            if (!((alive >> i) & 1u)) continue;
            float ax1 = __shfl_sync(FULL, x1, i);
            float ay1 = __shfl_sync(FULL, y1, i);
            float ax2 = __shfl_sync(FULL, x2, i);
            float ay2 = __shfl_sync(FULL, y2, i);
            float areaA = (ax2 - ax1) * (ay2 - ay1);
            float iw = fminf(ax2, x2) - fmaxf(ax1, x1);
            float ih = fminf(ay2, y2) - fmaxf(ay1, y1);
            float in0 = fmaxf(iw, 0.f) * fmaxf(ih, 0.f);
            float ar = (x2 - x1) * (y2 - y1);
            float iou = in0 / (areaA + ar - in0 + 1e-9f);
            u32 m = __ballot_sync(FULL, (lane > i) && (iou > IOUT));
            alive &= ~m;
        }

        int tot = __popc(alive);
        int base = 0;
        if (lane == 0) base = atomicAdd(&g_kcount[img], tot);
        base = __shfl_sync(FULL, base, 0);
        if ((alive >> lane) & 1u) {
            int p = base + __popc(alive & ((1u << lane) - 1u));
            if (p < KEPTCAP) g_kept[img * KEPTCAP + p] = k0;
        }
        return;
    }

    // ---- slow path: 64-element sort + NMS ----
    u64 k0 = lst[lane];
    u64 k1 = (lane + 32 < cnt) ? lst[lane + 32] : 0ull;

    #pragma unroll
    for (int k = 2; k <= 16; k <<= 1) {
        #pragma unroll
        for (int j = k >> 1; j > 0; j >>= 1) {
            bool d = ((lane & k) == 0);
            k0 = ce(k0, j, d, lane);
            k1 = ce(k1, j, d, lane);
        }
    }
    #pragma unroll
    for (int j = 16; j > 0; j >>= 1) {
        k0 = ce(k0, j, true, lane);
        k1 = ce(k1, j, false, lane);
    }
    {
        u64 lo = (k0 < k1) ? k0 : k1;
        u64 hi = (k0 < k1) ? k1 : k0;
        k0 = hi; k1 = lo;
    }
    #pragma unroll
    for (int j = 16; j > 0; j >>= 1) {
        k0 = ce(k0, j, true, lane);
        k1 = ce(k1, j, true, lane);
    }

    float x10, y10, x20, y20, x11, y11, x21, y21;
    decode_box(pred, img, k0, true,            x10, y10, x20, y20);
    decode_box(pred, img, k1, lane + 32 < cnt, x11, y11, x21, y21);

    u64 alive = (cnt >= 64) ? ~0ull : ((1ull << cnt) - 1ull);
    for (int i = 0; i < cnt; i++) {
        if (!((alive >> i) & 1ull)) continue;
        bool hi = (i >= 32);
        int  sl = i & 31;
        float sx1 = hi ? x11 : x10, sy1 = hi ? y11 : y10;
        float sx2 = hi ? x21 : x20, sy2 = hi ? y21 : y20;
        float ax1 = __shfl_sync(FULL, sx1, sl);
        float ay1 = __shfl_sync(FULL, sy1, sl);
        float ax2 = __shfl_sync(FULL, sx2, sl);
        float ay2 = __shfl_sync(FULL, sy2, sl);
        float areaA = (ax2 - ax1) * (ay2 - ay1);

        float iw0 = fminf(ax2, x20) - fmaxf(ax1, x10);
        float ih0 = fminf(ay2, y20) - fmaxf(ay1, y10);
        float in0 = fmaxf(iw0, 0.f) * fmaxf(ih0, 0.f);
        float ar0 = (x20 - x10) * (y20 - y10);
        float iou0 = in0 / (areaA + ar0 - in0 + 1e-9f);

        float iw1 = fminf(ax2, x21) - fmaxf(ax1, x11);
        float ih1 = fminf(ay2, y21) - fmaxf(ay1, y11);
        float in1 = fmaxf(iw1, 0.f) * fmaxf(ih1, 0.f);
        float ar1 = (x21 - x11) * (y21 - y11);
        float iou1 = in1 / (areaA + ar1 - in1 + 1e-9f);

        u32 m0 = __ballot_sync(FULL, (lane > i) && (iou0 > IOUT));
        u32 m1 = __ballot_sync(FULL, ((lane + 32) > i) && (iou1 > IOUT));
        alive &= ~(((u64)m1 << 32) | (u64)m0);
    }

    u32 klo = (u32)alive, khi = (u32)(alive >> 32);
    int tot = __popc(klo) + __popc(khi);
    int base = 0;
    if (lane == 0) base = atomicAdd(&g_kcount[img], tot);
    base = __shfl_sync(FULL, base, 0);
    if ((klo >> lane) & 1u) {
        int p = base + __popc(klo & ((1u << lane) - 1u));
        if (p < KEPTCAP) g_kept[img * KEPTCAP + p] = k0;
    }
    if ((khi >> lane) & 1u) {
        int p = base + __popc(klo) + __popc(khi & ((1u << lane) - 1u));
        if (p < KEPTCAP) g_kept[img * KEPTCAP + p] = k1;
    }
}

// ---------------------------------------------------------------------------
// K3: per image: 4096-bin score histogram + suffix scan -> contenders
// (strictly-above < 300); exact output rank by brute-force comparison among
// the ~305 contenders (keys unique); emit rows + zero-fill.
// ---------------------------------------------------------------------------
__global__ __launch_bounds__(1024) void k_out(const float* __restrict__ pred,
                                              float* __restrict__ out) {
    __shared__ u32 hist[NBIN];
    __shared__ u64 s_cont[CONTCAP];
    __shared__ u32 wsums[32];
    __shared__ int s_ccnt;

    int img  = blockIdx.x;
    int tid  = threadIdx.x;
    int lane = tid & 31;
    int warp = tid >> 5;

    int M = g_kcount[img];
    if (M > KEPTCAP) M = KEPTCAP;

    for (int i = tid; i < NBIN; i += 1024) hist[i] = 0;
    if (tid == 0) s_ccnt = 0;
    __syncthreads();

    const u64* kp = &g_kept[img * KEPTCAP];
    for (int i = tid; i < M; i += 1024) {
        u32 h = ((u32)(kp[i] >> 32) - SB0) >> 8;
        atomicAdd(&hist[h], 1u);
    }
    __syncthreads();

    // Suffix-exclusive scan over 4096 bins in place (4 bins/thread).
    int b0i = 4 * tid;
    u32 c0 = hist[b0i], c1 = hist[b0i + 1], c2 = hist[b0i + 2], c3 = hist[b0i + 3];
    u32 T = c0 + c1 + c2 + c3;
    u32 v = T;
    #pragma unroll
    for (int o = 1; o < 32; o <<= 1) {
        u32 u = __shfl_down_sync(FULL, v, o);
        if (lane + o < 32) v += u;
    }
    u32 exw = v - T;
    if (lane == 0) wsums[warp] = v;
    __syncthreads();
    if (warp == 0) {
        u32 wv = wsums[lane];
        u32 s = wv;
        #pragma unroll
        for (int o = 1; o < 32; o <<= 1) {
            u32 u = __shfl_down_sync(FULL, s, o);
            if (lane + o < 32) s += u;
        }
        wsums[lane] = s - wv;
    }
    __syncthreads();
    u32 above = wsums[warp] + exw;
    hist[b0i + 3] = above;
    hist[b0i + 2] = above + c3;
    hist[b0i + 1] = above + c3 + c2;
    hist[b0i + 0] = above + c3 + c2 + c1;
    __syncthreads();

    bool selAll = (M <= DETS);
    for (int i = tid; i < M; i += 1024) {
        u64 k = kp[i];
        u32 h = ((u32)(k >> 32) - SB0) >> 8;
        if (selAll || hist[h] < DETS) {
            int p = atomicAdd(&s_ccnt, 1);
            if (p < CONTCAP) s_cont[p] = k;
        }
    }
    __syncthreads();
    int S = s_ccnt; if (S > CONTCAP) S = CONTCAP;

    if (tid < S) {
        u64 key = s_cont[tid];
        int rank = 0;
        for (int j = 0; j < S; j++) rank += (s_cont[j] > key) ? 1 : 0;
        if (rank < DETS) {
            u32 idx = ~(u32)key;
            int a   = idx / NC;
            int cls = idx - a * NC;
            const float* p = pred + ((size_t)img * NANCH + a) * NCH;
            float cx = __ldg(p), cy = __ldg(p + 1);
            float w  = __ldg(p + 2), h = __ldg(p + 3);
            float* o = out + ((size_t)img * DETS + rank) * 6;
            o[0] = cx - 0.5f * w; o[1] = cy - 0.5f * h;
            o[2] = cx + 0.5f * w; o[3] = cy + 0.5f * h;
            o[4] = __uint_as_float((u32)(key >> 32));
            o[5] = (float)cls;
        }
    }

    int K = (M < DETS) ? M : DETS;
    for (int r = K + tid; r < DETS; r += 1024) {
        float* o = out + ((size_t)img * DETS + r) * 6;
        o[0] = 0.f; o[1] = 0.f; o[2] = 0.f; o[3] = 0.f; o[4] = 0.f; o[5] = 0.f;
    }
    __syncthreads();
    if (tid == 0) g_kcount[img] = 0;  // clean for next replay
}

extern "C" void kernel_launch(void* const* d_in, const int* in_sizes, int n_in,
                              void* d_out, int out_size) {
    const float* pred = (const float*)d_in[0];
    float* out = (float*)d_out;

    dim3 g1((NANCH + 255) / 256, NIMG);
    k_filter<<<g1, 256>>>(pred);
    k_nms<<<dim3(NIMG, 10), 256>>>(pred);
    k_out<<<NIMG, 1024>>>(pred, out);
}